// round 7
// baseline (speedup 1.0000x reference)
#include <cuda_runtime.h>
#include <math.h>

#define BB 8
#define TT 8192
#define DV 1024
#define DQ 768
#define KREP 6
#define NH 8
#define HD 128
#define CC 18
#define NBLK 128
#define NTHR 512

// ---------------- scratch (no allocations allowed) ----------------
__device__ __align__(16) float g_pre[2 * BB * DV];
__device__ __align__(16) float g_h[2 * BB * DV];
__device__ __align__(16) float g_mu[BB * DV];
__device__ __align__(16) float g_isg[BB * DV];
__device__ __align__(16) float g_rep[BB * KREP * DV];
__device__ __align__(16) float g_qkv[BB * KREP * 3 * DV];
__device__ __align__(16) float g_ao[BB * KREP * DV];
__device__ float g_attnw[BB * NH * KREP * KREP];
__device__ unsigned g_cnt = 0, g_gen = 0;

__device__ __forceinline__ float warp_sum(float v) {
#pragma unroll
    for (int o = 16; o; o >>= 1) v += __shfl_xor_sync(0xffffffffu, v, o);
    return v;
}

// software grid barrier: all NBLK blocks co-resident (128 blocks, 1/SM)
__device__ __forceinline__ void gbar() {
    __syncthreads();
    if (threadIdx.x == 0) {
        volatile unsigned* vgen = &g_gen;
        unsigned gen = *vgen;
        __threadfence();
        unsigned t = atomicAdd(&g_cnt, 1u);
        if (t == NBLK - 1) {
            atomicExch(&g_cnt, 0u);
            __threadfence();
            atomicAdd(&g_gen, 1u);
        } else {
            while (*vgen == gen) { }
            __threadfence();
        }
    }
    __syncthreads();
}

// one radix-select pass (512 threads, 2048 bins); `first` accepts all keys
__device__ void radix512(const unsigned* __restrict__ keys,
                         int shift, int bits, bool first,
                         unsigned* hist, unsigned* wsum, unsigned* wpfx,
                         unsigned* sh_prefix, int* sh_k) {
    int tid = threadIdx.x, lane = tid & 31, wid = tid >> 5;
#pragma unroll
    for (int j = 0; j < 4; j++) hist[tid + j * 512] = 0u;
    __syncthreads();
    unsigned pfx = *sh_prefix;
    unsigned mask = (1u << bits) - 1u;
#pragma unroll
    for (int r = 0; r < 16; r++) {
        unsigned key = keys[tid + r * 512];
        bool ok = first || ((key >> (shift + bits)) == pfx);
        if (ok) atomicAdd(&hist[(key >> shift) & mask], 1u);
    }
    __syncthreads();
    unsigned s0 = hist[tid * 4], s1 = hist[tid * 4 + 1],
             s2 = hist[tid * 4 + 2], s3 = hist[tid * 4 + 3];
    unsigned s = s0 + s1 + s2 + s3;
    unsigned inc = s;
#pragma unroll
    for (int o = 1; o < 32; o <<= 1) {
        unsigned n = __shfl_up_sync(0xffffffffu, inc, o);
        if (lane >= o) inc += n;
    }
    if (lane == 31) wsum[wid] = inc;   // 16 warps
    __syncthreads();
    if (wid == 0) {
        unsigned v = (lane < 16) ? wsum[lane] : 0u;
        unsigned iw = v;
#pragma unroll
        for (int o = 1; o < 32; o <<= 1) {
            unsigned n = __shfl_up_sync(0xffffffffu, iw, o);
            if (lane >= o) iw += n;
        }
        wpfx[lane] = iw - v;
    }
    __syncthreads();
    unsigned base = wpfx[wid] + (inc - s);
    unsigned k = (unsigned)*sh_k;
    if (k >= base && k < base + s) {   // exactly one thread
        int bin = tid * 4;
        unsigned off = base;
        if (k >= off + s0) { off += s0; bin++;
            if (k >= off + s1) { off += s1; bin++;
                if (k >= off + s2) { off += s2; bin++; } } }
        *sh_prefix = (pfx << bits) | (unsigned)bin;
        *sh_k = (int)(k - off);
    }
    __syncthreads();
}

// 48-row GEMM, 16 outputs per group, block-strided groups. SB >= 24KB.
__device__ void gemm_phase(const float* __restrict__ x, const float* __restrict__ w,
                           const float* __restrict__ bias, float* __restrict__ out,
                           int ostride, int ngroups, unsigned char* SB) {
    float4* xs = (float4*)SB;  // 1536 float4 = 24KB
    int tid = threadIdx.x, lane = tid & 31, wid = tid >> 5;
    for (int grp = blockIdx.x; grp < ngroups; grp += NBLK) {
        int o = grp * 16 + wid;
        const float4* wr = (const float4*)(w + o * DV);
        float acc[48];
#pragma unroll
        for (int r = 0; r < 48; r++) acc[r] = 0.f;
        for (int kc = 0; kc < 8; kc++) {
            __syncthreads();
#pragma unroll
            for (int j = 0; j < 3; j++) {
                int i = tid + j * 512;
                xs[i] = ((const float4*)(x + (i >> 5) * DV + kc * 128))[i & 31];
            }
            __syncthreads();
            float4 wv = wr[kc * 32 + lane];
#pragma unroll
            for (int r = 0; r < 48; r++) {
                float4 xv = xs[r * 32 + lane];
                acc[r] += wv.x * xv.x + wv.y * xv.y + wv.z * xv.z + wv.w * xv.w;
            }
        }
#pragma unroll
        for (int off = 16; off; off >>= 1)
#pragma unroll
            for (int r = 0; r < 48; r++)
                acc[r] += __shfl_xor_sync(0xffffffffu, acc[r], off);
        float bs = bias[o];
#pragma unroll
        for (int r = 0; r < 48; r++)
            if (lane == (r & 31)) out[r * ostride + o] = acc[r] + bs;
    }
}

__global__ __launch_bounds__(NTHR, 1) void k_all(
    const float* __restrict__ vf, const float* __restrict__ qe,
    const float* __restrict__ mu_w1, const float* __restrict__ mu_b1,
    const float* __restrict__ mu_g,  const float* __restrict__ mu_bt,
    const float* __restrict__ mu_w2, const float* __restrict__ mu_b2,
    const float* __restrict__ sg_w1, const float* __restrict__ sg_b1,
    const float* __restrict__ sg_g,  const float* __restrict__ sg_bt,
    const float* __restrict__ sg_w2, const float* __restrict__ sg_b2,
    const float* __restrict__ in_w,  const float* __restrict__ in_b,
    const float* __restrict__ out_w, const float* __restrict__ out_b,
    float* __restrict__ o_ref, float* __restrict__ o_idx,
    float* __restrict__ o_dist, float* __restrict__ o_mu,
    float* __restrict__ o_sg, float* __restrict__ o_attn) {

    __shared__ __align__(16) unsigned char SB[41728];
    __shared__ unsigned sh_prefix;
    __shared__ int sh_k, sh_n1, sh_n2;
    __shared__ int sels[KREP];
    __shared__ float sh_mean, sh_rstd;

    int tid = threadIdx.x, lane = tid & 31, wid = tid >> 5, blk = blockIdx.x;

    // ---- P0: Linear(768->1024) both branches, 16384 dots, 8/warp ----
    {
        int gw = blk * 16 + wid;  // 0..2047
#pragma unroll
        for (int d = 0; d < 8; d++) {
            int idx = gw * 8 + d;
            int br = idx >> 13;
            int rem = idx & 8191;
            int b = rem >> 10, o = rem & 1023;
            const float* w1 = br ? sg_w1 : mu_w1;
            const float* b1 = br ? sg_b1 : mu_b1;
            const float* x = qe + b * DQ;
            const float* wr = w1 + o * DQ;
            float acc = 0.f;
#pragma unroll
            for (int i = lane; i < DQ; i += 32) acc += wr[i] * x[i];
            acc = warp_sum(acc);
            if (lane == 0) g_pre[(br * BB + b) * DV + o] = acc + b1[o];
        }
    }
    gbar();

    // ---- P1a: LayerNorm + ReLU (blocks 0..15, one per (b,br)) ----
    if (blk < 16) {
        int b = blk >> 1, br = blk & 1;
        float* red = (float*)(SB + 4096);  // 16 partials
        const float* src = g_pre + (br * BB + b) * DV;
        float v0 = src[tid], v1 = src[tid + 512];
        float s = warp_sum(v0 + v1);
        if (lane == 0) red[wid] = s;
        __syncthreads();
        if (tid == 0) {
            float m = 0.f;
            for (int i = 0; i < 16; i++) m += red[i];
            sh_mean = m / (float)DV;
        }
        __syncthreads();
        float m = sh_mean;
        float d0 = v0 - m, d1 = v1 - m;
        float vv = warp_sum(d0 * d0 + d1 * d1);
        if (lane == 0) red[wid] = vv;
        __syncthreads();
        if (tid == 0) {
            float q = 0.f;
            for (int i = 0; i < 16; i++) q += red[i];
            sh_rstd = rsqrtf(q / (float)DV + 1e-5f);
        }
        __syncthreads();
        float rstd = sh_rstd;
        const float* g  = br ? sg_g  : mu_g;
        const float* bt = br ? sg_bt : mu_bt;
        float* dst = g_h + (br * BB + b) * DV;
        dst[tid]       = fmaxf(d0 * rstd * g[tid]       + bt[tid], 0.f);
        dst[tid + 512] = fmaxf(d1 * rstd * g[tid + 512] + bt[tid + 512], 0.f);
    }
    gbar();

    // ---- P1b: Linear(1024->1024) + mu/softplus epilogue ----
    {
        int gw = blk * 16 + wid;
#pragma unroll
        for (int d = 0; d < 8; d++) {
            int idx = gw * 8 + d;
            int br = idx >> 13;
            int rem = idx & 8191;
            int b = rem >> 10, o = rem & 1023;
            const float* w2 = br ? sg_w2 : mu_w2;
            const float* b2 = br ? sg_b2 : mu_b2;
            const float* x = g_h + (br * BB + b) * DV;
            const float* wr = w2 + o * DV;
            float acc = 0.f;
#pragma unroll
            for (int i = lane; i < DV; i += 32) acc += wr[i] * x[i];
            acc = warp_sum(acc);
            if (lane == 0) {
                float val = acc + b2[o];
                if (br == 0) {
                    g_mu[b * DV + o] = val;
                    o_mu[b * DV + o] = val;
                } else {
                    float sp = fmaxf(val, 0.f) + log1pf(expf(-fabsf(val)));
                    float sg = sp + 1e-6f;
                    o_sg[b * DV + o] = sg;
                    g_isg[b * DV + o] = 1.f / sg;
                }
            }
        }
    }
    gbar();

    // ---- P2: Mahalanobis distance, 256 MB stream; block = (b, chunk of 512 rows) ----
    {
        float4* mus = (float4*)SB;            // 256
        float4* iss = (float4*)(SB + 4096);   // 256
        int b = blk >> 4, chunk = blk & 15;
        if (tid < 256) mus[tid] = ((const float4*)(g_mu + b * DV))[tid];
        else if (tid < 512) iss[tid - 256] = ((const float4*)(g_isg + b * DV))[tid - 256];
        __syncthreads();
        for (int it = 0; it < 16; it++) {
            int t0 = chunk * 512 + (it * 16 + wid) * 2;
            const float4* v0 = (const float4*)(vf + ((size_t)b * TT + t0) * DV);
            const float4* v1 = v0 + DV / 4;
            float a0 = 0.f, a1 = 0.f;
#pragma unroll
            for (int k = 0; k < 8; k++) {
                int i = lane + k * 32;
                float4 x0 = v0[i], x1 = v1[i], mm = mus[i], ss = iss[i];
                float d;
                d = x0.x - mm.x; a0 += d * d * ss.x;
                d = x0.y - mm.y; a0 += d * d * ss.y;
                d = x0.z - mm.z; a0 += d * d * ss.z;
                d = x0.w - mm.w; a0 += d * d * ss.w;
                d = x1.x - mm.x; a1 += d * d * ss.x;
                d = x1.y - mm.y; a1 += d * d * ss.y;
                d = x1.z - mm.z; a1 += d * d * ss.z;
                d = x1.w - mm.w; a1 += d * d * ss.w;
            }
            a0 = warp_sum(a0);
            a1 = warp_sum(a1);
            if (lane == 0) {
                o_dist[b * TT + t0]     = a0;
                o_dist[b * TT + t0 + 1] = a1;
            }
        }
    }
    gbar();

    // ---- P3: median + top-18 + diversify + gather (blocks 0..7) ----
    if (blk < BB) {
        unsigned* keys = (unsigned*)SB;              // 8192 = 32KB
        unsigned* hist = (unsigned*)(SB + 32768);    // 2048 = 8KB
        unsigned* wsum = (unsigned*)(SB + 40960);
        unsigned* wpfx = (unsigned*)(SB + 41088);
        unsigned long long* lessK = (unsigned long long*)(SB + 41216);  // 18
        int* eqIdx = (int*)(SB + 41360);             // 64
        int b = blk;
        const float* drow = o_dist + b * TT;

#pragma unroll
        for (int r = 0; r < 16; r++)
            keys[tid + r * 512] = __float_as_uint(drow[tid + r * 512]);
        if (tid == 0) { sh_prefix = 0u; sh_k = (TT - 1) / 2; }
        __syncthreads();

        radix512(keys, 21, 11, true,  hist, wsum, wpfx, &sh_prefix, &sh_k);
        radix512(keys, 10, 11, false, hist, wsum, wpfx, &sh_prefix, &sh_k);
        radix512(keys,  0, 10, false, hist, wsum, wpfx, &sh_prefix, &sh_k);
        float med = __uint_as_float(sh_prefix);
        __syncthreads();

#pragma unroll
        for (int r = 0; r < 16; r++) {
            int i = tid + r * 512;
            keys[i] = __float_as_uint(fabsf(__uint_as_float(keys[i]) - med));
        }
        if (tid == 0) { sh_prefix = 0u; sh_k = CC - 1; sh_n1 = 0; sh_n2 = 0; }
        __syncthreads();

        radix512(keys, 21, 11, true,  hist, wsum, wpfx, &sh_prefix, &sh_k);
        radix512(keys, 10, 11, false, hist, wsum, wpfx, &sh_prefix, &sh_k);
        radix512(keys,  0, 10, false, hist, wsum, wpfx, &sh_prefix, &sh_k);
        unsigned vstar = sh_prefix;
        int n_eq_take = sh_k + 1;
        __syncthreads();

#pragma unroll
        for (int r = 0; r < 16; r++) {
            int i = tid + r * 512;
            unsigned key = keys[i];
            if (key < vstar) {
                int p = atomicAdd(&sh_n1, 1);
                lessK[p] = ((unsigned long long)key << 13) | (unsigned)i;
            } else if (key == vstar) {
                int p = atomicAdd(&sh_n2, 1);
                if (p < 64) eqIdx[p] = i;
            }
        }
        __syncthreads();

        if (tid == 0) {
            int nless = sh_n1;
            int neq = sh_n2 < 64 ? sh_n2 : 64;
            for (int i = 1; i < nless; i++) {
                unsigned long long kv = lessK[i];
                int j = i - 1;
                while (j >= 0 && lessK[j] > kv) { lessK[j + 1] = lessK[j]; j--; }
                lessK[j + 1] = kv;
            }
            for (int i = 1; i < neq; i++) {
                int kv = eqIdx[i];
                int j = i - 1;
                while (j >= 0 && eqIdx[j] > kv) { eqIdx[j + 1] = eqIdx[j]; j--; }
                eqIdx[j + 1] = kv;
            }
            int cand[CC];
            for (int c = 0; c < nless; c++) cand[c] = (int)(lessK[c] & 0x1FFFull);
            for (int c = 0; c < n_eq_take && nless + c < CC; c++) cand[nless + c] = eqIdx[c];

            const float NINF = __int_as_float(0xff800000);
            float candf[CC], mind[CC];
            int sel[KREP];
            for (int c = 0; c < CC; c++) candf[c] = (float)cand[c];
            for (int c = 0; c < CC; c++) mind[c] = fabsf(candf[c] - candf[0]);
            mind[0] = NINF;
            sel[0] = cand[0];
            for (int sI = 1; sI < KREP; sI++) {
                int best = 0;
                float bm = NINF;
                for (int c = 0; c < CC; c++)
                    if (mind[c] > bm) { bm = mind[c]; best = c; }
                sel[sI] = cand[best];
                float cb = candf[best];
                for (int c = 0; c < CC; c++) mind[c] = fminf(mind[c], fabsf(candf[c] - cb));
                mind[best] = NINF;
            }
            for (int sI = 0; sI < KREP; sI++) {
                sels[sI] = sel[sI];
                o_idx[b * KREP + sI] = (float)sel[sI];
            }
        }
        __syncthreads();

        for (int kk = 0; kk < KREP; kk++) {
            int t = sels[kk];
            const float* src = vf + ((size_t)b * TT + t) * DV;
            float* dst = g_rep + (b * KREP + kk) * DV;
            for (int i = tid; i < DV; i += NTHR) dst[i] = src[i];
        }
    }
    gbar();

    // ---- P4: QKV GEMM (3072 outputs = 192 groups) ----
    gemm_phase(g_rep, in_w, in_b, g_qkv, 3 * DV, 192, SB);
    gbar();

    // ---- P5: attention per (b,h) (blocks 0..63) ----
    if (blk < BB * NH) {
        int b = blk >> 3, h = blk & 7;
        float* qs = (float*)SB;
        float* ks = qs + KREP * HD;
        float* vs = ks + KREP * HD;
        for (int i = tid; i < KREP * HD; i += NTHR) {
            int row = i >> 7, d = i & 127;
            const float* base = g_qkv + (b * KREP + row) * 3 * DV + h * HD + d;
            qs[i] = base[0];
            ks[i] = base[DV];
            vs[i] = base[2 * DV];
        }
        __syncthreads();
        if (wid < KREP) {
            int i = wid;
            float sc[KREP];
            const float scale = 0.08838834764831845f;  // 1/sqrt(128)
            for (int j = 0; j < KREP; j++) {
                float acc = 0.f;
#pragma unroll
                for (int m = 0; m < 4; m++)
                    acc += qs[i * HD + lane + 32 * m] * ks[j * HD + lane + 32 * m];
                acc = warp_sum(acc);
                sc[j] = acc * scale;
            }
            float mx = sc[0];
            for (int j = 1; j < KREP; j++) mx = fmaxf(mx, sc[j]);
            float den = 0.f;
            for (int j = 0; j < KREP; j++) { sc[j] = expf(sc[j] - mx); den += sc[j]; }
            float rden = 1.f / den;
            for (int j = 0; j < KREP; j++) sc[j] *= rden;
            if (lane < KREP)
                g_attnw[((b * NH + h) * KREP + i) * KREP + lane] = sc[lane];
            for (int d = lane; d < HD; d += 32) {
                float o = 0.f;
                for (int j = 0; j < KREP; j++) o += sc[j] * vs[j * HD + d];
                g_ao[(b * KREP + i) * DV + h * HD + d] = o;
            }
        }
    }
    gbar();

    // ---- P6: attn-weight head-mean (blocks 0..7) + output projection ----
    if (blk < BB && tid < KREP * KREP) {
        int b = blk;
        float s = 0.f;
        for (int h = 0; h < NH; h++) s += g_attnw[(b * NH + h) * KREP * KREP + tid];
        o_attn[b * KREP * KREP + tid] = s * (1.f / (float)NH);
    }
    gemm_phase(g_ao, out_w, out_b, o_ref, DV, 64, SB);
}

// ---------------- launcher: ONE kernel ----------------
extern "C" void kernel_launch(void* const* d_in, const int* in_sizes, int n_in,
                              void* d_out, int out_size) {
    const float* vf    = (const float*)d_in[0];
    const float* qe    = (const float*)d_in[1];
    const float* mu_w1 = (const float*)d_in[2];
    const float* mu_b1 = (const float*)d_in[3];
    const float* mu_g  = (const float*)d_in[4];
    const float* mu_bt = (const float*)d_in[5];
    const float* mu_w2 = (const float*)d_in[6];
    const float* mu_b2 = (const float*)d_in[7];
    const float* sg_w1 = (const float*)d_in[8];
    const float* sg_b1 = (const float*)d_in[9];
    const float* sg_g  = (const float*)d_in[10];
    const float* sg_bt = (const float*)d_in[11];
    const float* sg_w2 = (const float*)d_in[12];
    const float* sg_b2 = (const float*)d_in[13];
    const float* in_w  = (const float*)d_in[14];
    const float* in_b  = (const float*)d_in[15];
    const float* out_w = (const float*)d_in[16];
    const float* out_b = (const float*)d_in[17];

    float* out = (float*)d_out;
    float* o_ref  = out;           // [8,6,1024]  49152
    float* o_idx  = out + 49152;   // [8,6]       48
    float* o_dist = out + 49200;   // [8,8192]    65536
    float* o_mu   = out + 114736;  // [8,1024]    8192
    float* o_sg   = out + 122928;  // [8,1024]    8192
    float* o_attn = out + 131120;  // [8,6,6]     288

    k_all<<<NBLK, NTHR>>>(vf, qe, mu_w1, mu_b1, mu_g, mu_bt, mu_w2, mu_b2,
                          sg_w1, sg_b1, sg_g, sg_bt, sg_w2, sg_b2,
                          in_w, in_b, out_w, out_b,
                          o_ref, o_idx, o_dist, o_mu, o_sg, o_attn);
}

// round 8
// speedup vs baseline: 1.1263x; 1.1263x over previous
#include <cuda_runtime.h>
#include <math.h>

#define BB 8
#define TT 8192
#define DV 1024
#define DQ 768
#define KREP 6
#define NH 8
#define HD 128
#define CC 18
#define NB 2048
#define NBLK 128

// ---------------- scratch (no allocations allowed) ----------------
__device__ __align__(16) float g_pre[2 * BB * DV];
__device__ __align__(16) float g_h[2 * BB * DV];
__device__ __align__(16) float g_mu[BB * DV];
__device__ __align__(16) float g_isg[BB * DV];
__device__ __align__(16) float g_rep[BB * KREP * DV];
__device__ __align__(16) float g_qkv[BB * KREP * 3 * DV];
__device__ __align__(16) float g_ao[BB * KREP * DV];
__device__ float g_attnw[BB * NH * KREP * KREP];
__device__ unsigned g_cnt = 0, g_gen = 0;

__device__ __forceinline__ float warp_sum(float v) {
#pragma unroll
    for (int o = 16; o; o >>= 1) v += __shfl_xor_sync(0xffffffffu, v, o);
    return v;
}

// software grid barrier: NBLK blocks, all co-resident (1 block/SM)
__device__ __forceinline__ void gbar() {
    __syncthreads();
    if (threadIdx.x == 0) {
        volatile unsigned* vgen = &g_gen;
        unsigned gen = *vgen;
        __threadfence();
        unsigned t = atomicAdd(&g_cnt, 1u);
        if (t == NBLK - 1) {
            atomicExch(&g_cnt, 0u);
            __threadfence();
            atomicAdd(&g_gen, 1u);
        } else {
            while (*vgen == gen) { }
            __threadfence();
        }
    }
    __syncthreads();
}

// ================= kernel 1: MLP (lin1 -> LN -> lin2), persistent =================
__global__ __launch_bounds__(512, 1) void k_mlp(
    const float* __restrict__ qe,
    const float* __restrict__ mu_w1, const float* __restrict__ mu_b1,
    const float* __restrict__ mu_g,  const float* __restrict__ mu_bt,
    const float* __restrict__ mu_w2, const float* __restrict__ mu_b2,
    const float* __restrict__ sg_w1, const float* __restrict__ sg_b1,
    const float* __restrict__ sg_g,  const float* __restrict__ sg_bt,
    const float* __restrict__ sg_w2, const float* __restrict__ sg_b2,
    float* __restrict__ o_mu, float* __restrict__ o_sg) {

    __shared__ float red[16];
    __shared__ float sh_mean, sh_rstd;
    int tid = threadIdx.x, lane = tid & 31, wid = tid >> 5, blk = blockIdx.x;

    // ---- P0: Linear(768->1024) both branches: 16384 dots, 8/warp ----
    {
        int gw = blk * 16 + wid;  // 0..2047
#pragma unroll
        for (int d = 0; d < 8; d++) {
            int idx = gw * 8 + d;
            int br = idx >> 13;
            int rem = idx & 8191;
            int b = rem >> 10, o = rem & 1023;
            const float* w1 = br ? sg_w1 : mu_w1;
            const float* b1 = br ? sg_b1 : mu_b1;
            const float* x = qe + b * DQ;
            const float* wr = w1 + o * DQ;
            float acc = 0.f;
#pragma unroll
            for (int i = lane; i < DQ; i += 32) acc += wr[i] * x[i];
            acc = warp_sum(acc);
            if (lane == 0) g_pre[(br * BB + b) * DV + o] = acc + b1[o];
        }
    }
    gbar();

    // ---- P1: LayerNorm + ReLU (blocks 0..15, one per (b,br)) ----
    if (blk < 16) {
        int b = blk >> 1, br = blk & 1;
        const float* src = g_pre + (br * BB + b) * DV;
        float v0 = src[tid], v1 = src[tid + 512];
        float s = warp_sum(v0 + v1);
        if (lane == 0) red[wid] = s;
        __syncthreads();
        if (tid == 0) {
            float m = 0.f;
            for (int i = 0; i < 16; i++) m += red[i];
            sh_mean = m / (float)DV;
        }
        __syncthreads();
        float m = sh_mean;
        float d0 = v0 - m, d1 = v1 - m;
        float vv = warp_sum(d0 * d0 + d1 * d1);
        if (lane == 0) red[wid] = vv;
        __syncthreads();
        if (tid == 0) {
            float q = 0.f;
            for (int i = 0; i < 16; i++) q += red[i];
            sh_rstd = rsqrtf(q / (float)DV + 1e-5f);
        }
        __syncthreads();
        float rstd = sh_rstd;
        const float* g  = br ? sg_g  : mu_g;
        const float* bt = br ? sg_bt : mu_bt;
        float* dst = g_h + (br * BB + b) * DV;
        dst[tid]       = fmaxf(d0 * rstd * g[tid]       + bt[tid], 0.f);
        dst[tid + 512] = fmaxf(d1 * rstd * g[tid + 512] + bt[tid + 512], 0.f);
    }
    gbar();

    // ---- P2: Linear(1024->1024) + mu/softplus epilogue ----
    {
        int gw = blk * 16 + wid;
#pragma unroll
        for (int d = 0; d < 8; d++) {
            int idx = gw * 8 + d;
            int br = idx >> 13;
            int rem = idx & 8191;
            int b = rem >> 10, o = rem & 1023;
            const float* w2 = br ? sg_w2 : mu_w2;
            const float* b2 = br ? sg_b2 : mu_b2;
            const float* x = g_h + (br * BB + b) * DV;
            const float* wr = w2 + o * DV;
            float acc = 0.f;
#pragma unroll
            for (int i = lane; i < DV; i += 32) acc += wr[i] * x[i];
            acc = warp_sum(acc);
            if (lane == 0) {
                float val = acc + b2[o];
                if (br == 0) {
                    g_mu[b * DV + o] = val;
                    o_mu[b * DV + o] = val;
                } else {
                    float sp = fmaxf(val, 0.f) + log1pf(expf(-fabsf(val)));
                    float sg = sp + 1e-6f;
                    o_sg[b * DV + o] = sg;
                    g_isg[b * DV + o] = 1.f / sg;
                }
            }
        }
    }
}

// ================= kernel 2: Mahalanobis distance (wide grid, R6-proven) =================
__global__ void k_dist(const float* __restrict__ vf, float* __restrict__ o_dist) {
    __shared__ float4 mus[DV / 4];
    __shared__ float4 iss[DV / 4];
    int b = blockIdx.y;
    int tid = threadIdx.x, lane = tid & 31, wid = tid >> 5;
    if (tid < 256) mus[tid] = ((const float4*)(g_mu + b * DV))[tid];
    else           iss[tid - 256] = ((const float4*)(g_isg + b * DV))[tid - 256];
    __syncthreads();

    int t0 = (blockIdx.x * 16 + wid) * 2;
    const float4* v0 = (const float4*)(vf + ((size_t)b * TT + t0) * DV);
    const float4* v1 = v0 + DV / 4;
    float a0 = 0.f, a1 = 0.f;
#pragma unroll
    for (int it = 0; it < 8; it++) {
        int i = lane + it * 32;
        float4 x0 = v0[i], x1 = v1[i], mm = mus[i], ss = iss[i];
        float d;
        d = x0.x - mm.x; a0 += d * d * ss.x;
        d = x0.y - mm.y; a0 += d * d * ss.y;
        d = x0.z - mm.z; a0 += d * d * ss.z;
        d = x0.w - mm.w; a0 += d * d * ss.w;
        d = x1.x - mm.x; a1 += d * d * ss.x;
        d = x1.y - mm.y; a1 += d * d * ss.y;
        d = x1.z - mm.z; a1 += d * d * ss.z;
        d = x1.w - mm.w; a1 += d * d * ss.w;
    }
    a0 = warp_sum(a0);
    a1 = warp_sum(a1);
    if (lane == 0) {
        o_dist[b * TT + t0]     = a0;
        o_dist[b * TT + t0 + 1] = a1;
    }
}

// ================= kernel 3: select (R6-proven, 8 x 1024) =================
__device__ void radix_pass_s(const unsigned* __restrict__ keys,
                             int shift, int bits, bool first,
                             unsigned* hist, unsigned* wsum, unsigned* wpfx,
                             unsigned* sh_prefix, int* sh_k) {
    int tid = threadIdx.x, lane = tid & 31, wid = tid >> 5;
    hist[tid] = 0u;
    hist[tid + 1024] = 0u;
    __syncthreads();
    unsigned pfx = *sh_prefix;
    unsigned mask = (1u << bits) - 1u;
#pragma unroll
    for (int r = 0; r < 8; r++) {
        unsigned key = keys[tid + r * 1024];
        bool ok = first || ((key >> (shift + bits)) == pfx);
        if (ok) atomicAdd(&hist[(key >> shift) & mask], 1u);
    }
    __syncthreads();
    unsigned s0 = hist[tid * 2], s1 = hist[tid * 2 + 1];
    unsigned s = s0 + s1;
    unsigned inc = s;
#pragma unroll
    for (int o = 1; o < 32; o <<= 1) {
        unsigned n = __shfl_up_sync(0xffffffffu, inc, o);
        if (lane >= o) inc += n;
    }
    if (lane == 31) wsum[wid] = inc;
    __syncthreads();
    if (wid == 0) {
        unsigned v = wsum[lane];
        unsigned iw = v;
#pragma unroll
        for (int o = 1; o < 32; o <<= 1) {
            unsigned n = __shfl_up_sync(0xffffffffu, iw, o);
            if (lane >= o) iw += n;
        }
        wpfx[lane] = iw - v;
    }
    __syncthreads();
    unsigned base = wpfx[wid] + (inc - s);
    unsigned k = (unsigned)*sh_k;
    if (k >= base && k < base + s) {
        int bin = tid * 2;
        unsigned off = base;
        if (k >= off + s0) { off += s0; bin++; }
        *sh_prefix = (pfx << bits) | (unsigned)bin;
        *sh_k = (int)(k - off);
    }
    __syncthreads();
}

__global__ void k_select(const float* __restrict__ dist, const float* __restrict__ vf,
                         float* __restrict__ o_idx) {
    __shared__ unsigned keys[TT];
    __shared__ unsigned hist[NB];
    __shared__ unsigned wsum[32], wpfx[32];
    __shared__ unsigned sh_prefix;
    __shared__ int sh_k;
    __shared__ unsigned long long lessK[CC];
    __shared__ int eqIdx[64];
    __shared__ int sh_nless, sh_neq;
    __shared__ int sels[KREP];

    int b = blockIdx.x;
    int tid = threadIdx.x;
    const float* drow = dist + b * TT;

#pragma unroll
    for (int r = 0; r < 8; r++)
        keys[tid + r * 1024] = __float_as_uint(drow[tid + r * 1024]);
    if (tid == 0) { sh_prefix = 0u; sh_k = (TT - 1) / 2; }
    __syncthreads();

    radix_pass_s(keys, 21, 11, true,  hist, wsum, wpfx, &sh_prefix, &sh_k);
    radix_pass_s(keys, 10, 11, false, hist, wsum, wpfx, &sh_prefix, &sh_k);
    radix_pass_s(keys,  0, 10, false, hist, wsum, wpfx, &sh_prefix, &sh_k);
    float med = __uint_as_float(sh_prefix);
    __syncthreads();

#pragma unroll
    for (int r = 0; r < 8; r++) {
        int i = tid + r * 1024;
        keys[i] = __float_as_uint(fabsf(__uint_as_float(keys[i]) - med));
    }
    if (tid == 0) { sh_prefix = 0u; sh_k = CC - 1; sh_nless = 0; sh_neq = 0; }
    __syncthreads();

    radix_pass_s(keys, 21, 11, true,  hist, wsum, wpfx, &sh_prefix, &sh_k);
    radix_pass_s(keys, 10, 11, false, hist, wsum, wpfx, &sh_prefix, &sh_k);
    radix_pass_s(keys,  0, 10, false, hist, wsum, wpfx, &sh_prefix, &sh_k);
    unsigned vstar = sh_prefix;
    int n_eq_take = sh_k + 1;
    __syncthreads();

#pragma unroll
    for (int r = 0; r < 8; r++) {
        int i = tid + r * 1024;
        unsigned key = keys[i];
        if (key < vstar) {
            int p = atomicAdd(&sh_nless, 1);
            lessK[p] = ((unsigned long long)key << 13) | (unsigned)i;
        } else if (key == vstar) {
            int p = atomicAdd(&sh_neq, 1);
            if (p < 64) eqIdx[p] = i;
        }
    }
    __syncthreads();

    if (tid == 0) {
        int nless = sh_nless;
        int neq = sh_neq < 64 ? sh_neq : 64;
        for (int i = 1; i < nless; i++) {
            unsigned long long kv = lessK[i];
            int j = i - 1;
            while (j >= 0 && lessK[j] > kv) { lessK[j + 1] = lessK[j]; j--; }
            lessK[j + 1] = kv;
        }
        for (int i = 1; i < neq; i++) {
            int kv = eqIdx[i];
            int j = i - 1;
            while (j >= 0 && eqIdx[j] > kv) { eqIdx[j + 1] = eqIdx[j]; j--; }
            eqIdx[j + 1] = kv;
        }
        int cand[CC];
        for (int c = 0; c < nless; c++) cand[c] = (int)(lessK[c] & 0x1FFFull);
        for (int c = 0; c < n_eq_take && nless + c < CC; c++) cand[nless + c] = eqIdx[c];

        const float NINF = __int_as_float(0xff800000);
        float candf[CC], mind[CC];
        int sel[KREP];
        for (int c = 0; c < CC; c++) candf[c] = (float)cand[c];
        for (int c = 0; c < CC; c++) mind[c] = fabsf(candf[c] - candf[0]);
        mind[0] = NINF;
        sel[0] = cand[0];
        for (int sI = 1; sI < KREP; sI++) {
            int best = 0;
            float bm = NINF;
            for (int c = 0; c < CC; c++)
                if (mind[c] > bm) { bm = mind[c]; best = c; }
            sel[sI] = cand[best];
            float cb = candf[best];
            for (int c = 0; c < CC; c++) mind[c] = fminf(mind[c], fabsf(candf[c] - cb));
            mind[best] = NINF;
        }
        for (int sI = 0; sI < KREP; sI++) {
            sels[sI] = sel[sI];
            o_idx[b * KREP + sI] = (float)sel[sI];
        }
    }
    __syncthreads();

    for (int kk = 0; kk < KREP; kk++) {
        int t = sels[kk];
        const float* src = vf + ((size_t)b * TT + t) * DV;
        float* dst = g_rep + (b * KREP + kk) * DV;
        if (tid < DV) dst[tid] = src[tid];
    }
}

// ================= kernel 4: post (QKV -> attn -> mean+oproj), persistent =================
__device__ void gemm_phase(const float* __restrict__ x, const float* __restrict__ w,
                           const float* __restrict__ bias, float* __restrict__ out,
                           int ostride, int ngroups, float4* xs) {
    int tid = threadIdx.x, lane = tid & 31, wid = tid >> 5;
    for (int grp = blockIdx.x; grp < ngroups; grp += NBLK) {
        int o = grp * 16 + wid;
        const float4* wr = (const float4*)(w + o * DV);
        float acc[48];
#pragma unroll
        for (int r = 0; r < 48; r++) acc[r] = 0.f;
        for (int kc = 0; kc < 8; kc++) {
            __syncthreads();
#pragma unroll
            for (int j = 0; j < 3; j++) {
                int i = tid + j * 512;
                xs[i] = ((const float4*)(x + (i >> 5) * DV + kc * 128))[i & 31];
            }
            __syncthreads();
            float4 wv = wr[kc * 32 + lane];
#pragma unroll
            for (int r = 0; r < 48; r++) {
                float4 xv = xs[r * 32 + lane];
                acc[r] += wv.x * xv.x + wv.y * xv.y + wv.z * xv.z + wv.w * xv.w;
            }
        }
#pragma unroll
        for (int off = 16; off; off >>= 1)
#pragma unroll
            for (int r = 0; r < 48; r++)
                acc[r] += __shfl_xor_sync(0xffffffffu, acc[r], off);
        float bs = bias[o];
#pragma unroll
        for (int r = 0; r < 48; r++)
            if (lane == (r & 31)) out[r * ostride + o] = acc[r] + bs;
    }
}

__global__ __launch_bounds__(512, 1) void k_post(
    const float* __restrict__ in_w,  const float* __restrict__ in_b,
    const float* __restrict__ out_w, const float* __restrict__ out_b,
    float* __restrict__ o_ref, float* __restrict__ o_attn) {

    __shared__ __align__(16) float4 xs[48 * 32];  // 24KB (also hosts attn tiles)
    int tid = threadIdx.x, lane = tid & 31, wid = tid >> 5, blk = blockIdx.x;

    // ---- P0: QKV GEMM (192 groups) ----
    gemm_phase(g_rep, in_w, in_b, g_qkv, 3 * DV, 192, xs);
    gbar();

    // ---- P1: attention per (b,h) (blocks 0..63) ----
    if (blk < BB * NH) {
        int b = blk >> 3, h = blk & 7;
        float* qs = (float*)xs;
        float* ks = qs + KREP * HD;
        float* vs = ks + KREP * HD;
        for (int i = tid; i < KREP * HD; i += 512) {
            int row = i >> 7, d = i & 127;
            const float* base = g_qkv + (b * KREP + row) * 3 * DV + h * HD + d;
            qs[i] = base[0];
            ks[i] = base[DV];
            vs[i] = base[2 * DV];
        }
        __syncthreads();
        if (wid < KREP) {
            int i = wid;
            float sc[KREP];
            const float scale = 0.08838834764831845f;  // 1/sqrt(128)
            for (int j = 0; j < KREP; j++) {
                float acc = 0.f;
#pragma unroll
                for (int m = 0; m < 4; m++)
                    acc += qs[i * HD + lane + 32 * m] * ks[j * HD + lane + 32 * m];
                acc = warp_sum(acc);
                sc[j] = acc * scale;
            }
            float mx = sc[0];
            for (int j = 1; j < KREP; j++) mx = fmaxf(mx, sc[j]);
            float den = 0.f;
            for (int j = 0; j < KREP; j++) { sc[j] = expf(sc[j] - mx); den += sc[j]; }
            float rden = 1.f / den;
            for (int j = 0; j < KREP; j++) sc[j] *= rden;
            if (lane < KREP)
                g_attnw[((b * NH + h) * KREP + i) * KREP + lane] = sc[lane];
            for (int d = lane; d < HD; d += 32) {
                float o = 0.f;
                for (int j = 0; j < KREP; j++) o += sc[j] * vs[j * HD + d];
                g_ao[(b * KREP + i) * DV + h * HD + d] = o;
            }
        }
    }
    gbar();

    // ---- P2: attn-weight head-mean (blocks 0..7) + output projection (64 groups) ----
    if (blk < BB && tid < KREP * KREP) {
        int b = blk;
        float s = 0.f;
        for (int h = 0; h < NH; h++) s += g_attnw[(b * NH + h) * KREP * KREP + tid];
        o_attn[b * KREP * KREP + tid] = s * (1.f / (float)NH);
    }
    gemm_phase(g_ao, out_w, out_b, o_ref, DV, 64, xs);
}

// ---------------- launcher ----------------
extern "C" void kernel_launch(void* const* d_in, const int* in_sizes, int n_in,
                              void* d_out, int out_size) {
    const float* vf    = (const float*)d_in[0];
    const float* qe    = (const float*)d_in[1];
    const float* mu_w1 = (const float*)d_in[2];
    const float* mu_b1 = (const float*)d_in[3];
    const float* mu_g  = (const float*)d_in[4];
    const float* mu_bt = (const float*)d_in[5];
    const float* mu_w2 = (const float*)d_in[6];
    const float* mu_b2 = (const float*)d_in[7];
    const float* sg_w1 = (const float*)d_in[8];
    const float* sg_b1 = (const float*)d_in[9];
    const float* sg_g  = (const float*)d_in[10];
    const float* sg_bt = (const float*)d_in[11];
    const float* sg_w2 = (const float*)d_in[12];
    const float* sg_b2 = (const float*)d_in[13];
    const float* in_w  = (const float*)d_in[14];
    const float* in_b  = (const float*)d_in[15];
    const float* out_w = (const float*)d_in[16];
    const float* out_b = (const float*)d_in[17];

    float* out = (float*)d_out;
    float* o_ref  = out;           // [8,6,1024]  49152
    float* o_idx  = out + 49152;   // [8,6]       48
    float* o_dist = out + 49200;   // [8,8192]    65536
    float* o_mu   = out + 114736;  // [8,1024]    8192
    float* o_sg   = out + 122928;  // [8,1024]    8192
    float* o_attn = out + 131120;  // [8,6,6]     288

    k_mlp<<<NBLK, 512>>>(qe, mu_w1, mu_b1, mu_g, mu_bt, mu_w2, mu_b2,
                         sg_w1, sg_b1, sg_g, sg_bt, sg_w2, sg_b2, o_mu, o_sg);
    k_dist<<<dim3(TT / 32, BB), 512>>>(vf, o_dist);
    k_select<<<BB, 1024>>>(o_dist, vf, o_idx);
    k_post<<<NBLK, 512>>>(in_w, in_b, out_w, out_b, o_ref, o_attn);
}

// round 9
// speedup vs baseline: 1.2843x; 1.1403x over previous
#include <cuda_runtime.h>
#include <math.h>

#define BB 8
#define TT 8192
#define DV 1024
#define DQ 768
#define KREP 6
#define NH 8
#define HD 128
#define CC 18
#define NB 2048
#define NBLK 128

// ---------------- scratch (no allocations allowed) ----------------
__device__ __align__(16) float g_pre[2 * BB * DV];
__device__ __align__(16) float g_h[2 * BB * DV];
__device__ __align__(16) float g_mu[BB * DV];
__device__ __align__(16) float g_isg[BB * DV];
__device__ __align__(16) float g_rep[BB * KREP * DV];
__device__ __align__(16) float g_qkv[BB * KREP * 3 * DV];
__device__ __align__(16) float g_ao[BB * KREP * DV];
__device__ float g_attnw[BB * NH * KREP * KREP];
__device__ unsigned g_cnt = 0, g_gen = 0;

__device__ __forceinline__ float warp_sum(float v) {
#pragma unroll
    for (int o = 16; o; o >>= 1) v += __shfl_xor_sync(0xffffffffu, v, o);
    return v;
}

// software grid barrier: NBLK blocks, all co-resident (1 block/SM)
__device__ __forceinline__ void gbar() {
    __syncthreads();
    if (threadIdx.x == 0) {
        volatile unsigned* vgen = &g_gen;
        unsigned gen = *vgen;
        __threadfence();
        unsigned t = atomicAdd(&g_cnt, 1u);
        if (t == NBLK - 1) {
            atomicExch(&g_cnt, 0u);
            __threadfence();
            atomicAdd(&g_gen, 1u);
        } else {
            while (*vgen == gen) { }
            __threadfence();
        }
    }
    __syncthreads();
}

// ================= kernel 1: MLP (lin1 -> LN -> lin2), persistent =================
__global__ __launch_bounds__(512, 1) void k_mlp(
    const float* __restrict__ qe,
    const float* __restrict__ mu_w1, const float* __restrict__ mu_b1,
    const float* __restrict__ mu_g,  const float* __restrict__ mu_bt,
    const float* __restrict__ mu_w2, const float* __restrict__ mu_b2,
    const float* __restrict__ sg_w1, const float* __restrict__ sg_b1,
    const float* __restrict__ sg_g,  const float* __restrict__ sg_bt,
    const float* __restrict__ sg_w2, const float* __restrict__ sg_b2,
    float* __restrict__ o_mu, float* __restrict__ o_sg) {

    __shared__ float red[16];
    __shared__ float sh_mean, sh_rstd;
    int tid = threadIdx.x, lane = tid & 31, wid = tid >> 5, blk = blockIdx.x;

    // ---- P0: Linear(768->1024) both branches: 16384 dots, 8/warp ----
    {
        int gw = blk * 16 + wid;  // 0..2047
#pragma unroll
        for (int d = 0; d < 8; d++) {
            int idx = gw * 8 + d;
            int br = idx >> 13;
            int rem = idx & 8191;
            int b = rem >> 10, o = rem & 1023;
            const float* w1 = br ? sg_w1 : mu_w1;
            const float* b1 = br ? sg_b1 : mu_b1;
            const float* x = qe + b * DQ;
            const float* wr = w1 + o * DQ;
            float acc = 0.f;
#pragma unroll
            for (int i = lane; i < DQ; i += 32) acc += wr[i] * x[i];
            acc = warp_sum(acc);
            if (lane == 0) g_pre[(br * BB + b) * DV + o] = acc + b1[o];
        }
    }
    gbar();

    // ---- P1: LayerNorm + ReLU (blocks 0..15, one per (b,br)) ----
    if (blk < 16) {
        int b = blk >> 1, br = blk & 1;
        const float* src = g_pre + (br * BB + b) * DV;
        float v0 = src[tid], v1 = src[tid + 512];
        float s = warp_sum(v0 + v1);
        if (lane == 0) red[wid] = s;
        __syncthreads();
        if (tid == 0) {
            float m = 0.f;
            for (int i = 0; i < 16; i++) m += red[i];
            sh_mean = m / (float)DV;
        }
        __syncthreads();
        float m = sh_mean;
        float d0 = v0 - m, d1 = v1 - m;
        float vv = warp_sum(d0 * d0 + d1 * d1);
        if (lane == 0) red[wid] = vv;
        __syncthreads();
        if (tid == 0) {
            float q = 0.f;
            for (int i = 0; i < 16; i++) q += red[i];
            sh_rstd = rsqrtf(q / (float)DV + 1e-5f);
        }
        __syncthreads();
        float rstd = sh_rstd;
        const float* g  = br ? sg_g  : mu_g;
        const float* bt = br ? sg_bt : mu_bt;
        float* dst = g_h + (br * BB + b) * DV;
        dst[tid]       = fmaxf(d0 * rstd * g[tid]       + bt[tid], 0.f);
        dst[tid + 512] = fmaxf(d1 * rstd * g[tid + 512] + bt[tid + 512], 0.f);
    }
    gbar();

    // ---- P2: Linear(1024->1024) + mu/softplus epilogue ----
    {
        int gw = blk * 16 + wid;
#pragma unroll
        for (int d = 0; d < 8; d++) {
            int idx = gw * 8 + d;
            int br = idx >> 13;
            int rem = idx & 8191;
            int b = rem >> 10, o = rem & 1023;
            const float* w2 = br ? sg_w2 : mu_w2;
            const float* b2 = br ? sg_b2 : mu_b2;
            const float* x = g_h + (br * BB + b) * DV;
            const float* wr = w2 + o * DV;
            float acc = 0.f;
#pragma unroll
            for (int i = lane; i < DV; i += 32) acc += wr[i] * x[i];
            acc = warp_sum(acc);
            if (lane == 0) {
                float val = acc + b2[o];
                if (br == 0) {
                    g_mu[b * DV + o] = val;
                    o_mu[b * DV + o] = val;
                } else {
                    float sp = fmaxf(val, 0.f) + log1pf(expf(-fabsf(val)));
                    float sg = sp + 1e-6f;
                    o_sg[b * DV + o] = sg;
                    g_isg[b * DV + o] = 1.f / sg;
                }
            }
        }
    }
}

// ================= kernel 2: Mahalanobis distance (wide grid, proven) =================
__global__ void k_dist(const float* __restrict__ vf, float* __restrict__ o_dist) {
    __shared__ float4 mus[DV / 4];
    __shared__ float4 iss[DV / 4];
    int b = blockIdx.y;
    int tid = threadIdx.x, lane = tid & 31, wid = tid >> 5;
    if (tid < 256) mus[tid] = ((const float4*)(g_mu + b * DV))[tid];
    else           iss[tid - 256] = ((const float4*)(g_isg + b * DV))[tid - 256];
    __syncthreads();

    int t0 = (blockIdx.x * 16 + wid) * 2;
    const float4* v0 = (const float4*)(vf + ((size_t)b * TT + t0) * DV);
    const float4* v1 = v0 + DV / 4;
    float a0 = 0.f, a1 = 0.f;
#pragma unroll
    for (int it = 0; it < 8; it++) {
        int i = lane + it * 32;
        float4 x0 = v0[i], x1 = v1[i], mm = mus[i], ss = iss[i];
        float d;
        d = x0.x - mm.x; a0 += d * d * ss.x;
        d = x0.y - mm.y; a0 += d * d * ss.y;
        d = x0.z - mm.z; a0 += d * d * ss.z;
        d = x0.w - mm.w; a0 += d * d * ss.w;
        d = x1.x - mm.x; a1 += d * d * ss.x;
        d = x1.y - mm.y; a1 += d * d * ss.y;
        d = x1.z - mm.z; a1 += d * d * ss.z;
        d = x1.w - mm.w; a1 += d * d * ss.w;
    }
    a0 = warp_sum(a0);
    a1 = warp_sum(a1);
    if (lane == 0) {
        o_dist[b * TT + t0]     = a0;
        o_dist[b * TT + t0 + 1] = a1;
    }
}

// ================= kernel 3: select (proven, 8 x 1024) =================
__device__ void radix_pass_s(const unsigned* __restrict__ keys,
                             int shift, int bits, bool first,
                             unsigned* hist, unsigned* wsum, unsigned* wpfx,
                             unsigned* sh_prefix, int* sh_k) {
    int tid = threadIdx.x, lane = tid & 31, wid = tid >> 5;
    hist[tid] = 0u;
    hist[tid + 1024] = 0u;
    __syncthreads();
    unsigned pfx = *sh_prefix;
    unsigned mask = (1u << bits) - 1u;
#pragma unroll
    for (int r = 0; r < 8; r++) {
        unsigned key = keys[tid + r * 1024];
        bool ok = first || ((key >> (shift + bits)) == pfx);
        if (ok) atomicAdd(&hist[(key >> shift) & mask], 1u);
    }
    __syncthreads();
    unsigned s0 = hist[tid * 2], s1 = hist[tid * 2 + 1];
    unsigned s = s0 + s1;
    unsigned inc = s;
#pragma unroll
    for (int o = 1; o < 32; o <<= 1) {
        unsigned n = __shfl_up_sync(0xffffffffu, inc, o);
        if (lane >= o) inc += n;
    }
    if (lane == 31) wsum[wid] = inc;
    __syncthreads();
    if (wid == 0) {
        unsigned v = wsum[lane];
        unsigned iw = v;
#pragma unroll
        for (int o = 1; o < 32; o <<= 1) {
            unsigned n = __shfl_up_sync(0xffffffffu, iw, o);
            if (lane >= o) iw += n;
        }
        wpfx[lane] = iw - v;
    }
    __syncthreads();
    unsigned base = wpfx[wid] + (inc - s);
    unsigned k = (unsigned)*sh_k;
    if (k >= base && k < base + s) {
        int bin = tid * 2;
        unsigned off = base;
        if (k >= off + s0) { off += s0; bin++; }
        *sh_prefix = (pfx << bits) | (unsigned)bin;
        *sh_k = (int)(k - off);
    }
    __syncthreads();
}

__global__ void k_select(const float* __restrict__ dist, const float* __restrict__ vf,
                         float* __restrict__ o_idx) {
    __shared__ unsigned keys[TT];
    __shared__ unsigned hist[NB];
    __shared__ unsigned wsum[32], wpfx[32];
    __shared__ unsigned sh_prefix;
    __shared__ int sh_k;
    __shared__ unsigned long long lessK[CC];
    __shared__ int eqIdx[64];
    __shared__ int sh_nless, sh_neq;
    __shared__ int sels[KREP];

    int b = blockIdx.x;
    int tid = threadIdx.x;
    const float* drow = dist + b * TT;

#pragma unroll
    for (int r = 0; r < 8; r++)
        keys[tid + r * 1024] = __float_as_uint(drow[tid + r * 1024]);
    if (tid == 0) { sh_prefix = 0u; sh_k = (TT - 1) / 2; }
    __syncthreads();

    radix_pass_s(keys, 21, 11, true,  hist, wsum, wpfx, &sh_prefix, &sh_k);
    radix_pass_s(keys, 10, 11, false, hist, wsum, wpfx, &sh_prefix, &sh_k);
    radix_pass_s(keys,  0, 10, false, hist, wsum, wpfx, &sh_prefix, &sh_k);
    float med = __uint_as_float(sh_prefix);
    __syncthreads();

#pragma unroll
    for (int r = 0; r < 8; r++) {
        int i = tid + r * 1024;
        keys[i] = __float_as_uint(fabsf(__uint_as_float(keys[i]) - med));
    }
    if (tid == 0) { sh_prefix = 0u; sh_k = CC - 1; sh_nless = 0; sh_neq = 0; }
    __syncthreads();

    radix_pass_s(keys, 21, 11, true,  hist, wsum, wpfx, &sh_prefix, &sh_k);
    radix_pass_s(keys, 10, 11, false, hist, wsum, wpfx, &sh_prefix, &sh_k);
    radix_pass_s(keys,  0, 10, false, hist, wsum, wpfx, &sh_prefix, &sh_k);
    unsigned vstar = sh_prefix;
    int n_eq_take = sh_k + 1;
    __syncthreads();

#pragma unroll
    for (int r = 0; r < 8; r++) {
        int i = tid + r * 1024;
        unsigned key = keys[i];
        if (key < vstar) {
            int p = atomicAdd(&sh_nless, 1);
            lessK[p] = ((unsigned long long)key << 13) | (unsigned)i;
        } else if (key == vstar) {
            int p = atomicAdd(&sh_neq, 1);
            if (p < 64) eqIdx[p] = i;
        }
    }
    __syncthreads();

    if (tid == 0) {
        int nless = sh_nless;
        int neq = sh_neq < 64 ? sh_neq : 64;
        for (int i = 1; i < nless; i++) {
            unsigned long long kv = lessK[i];
            int j = i - 1;
            while (j >= 0 && lessK[j] > kv) { lessK[j + 1] = lessK[j]; j--; }
            lessK[j + 1] = kv;
        }
        for (int i = 1; i < neq; i++) {
            int kv = eqIdx[i];
            int j = i - 1;
            while (j >= 0 && eqIdx[j] > kv) { eqIdx[j + 1] = eqIdx[j]; j--; }
            eqIdx[j + 1] = kv;
        }
        int cand[CC];
        for (int c = 0; c < nless; c++) cand[c] = (int)(lessK[c] & 0x1FFFull);
        for (int c = 0; c < n_eq_take && nless + c < CC; c++) cand[nless + c] = eqIdx[c];

        const float NINF = __int_as_float(0xff800000);
        float candf[CC], mind[CC];
        int sel[KREP];
        for (int c = 0; c < CC; c++) candf[c] = (float)cand[c];
        for (int c = 0; c < CC; c++) mind[c] = fabsf(candf[c] - candf[0]);
        mind[0] = NINF;
        sel[0] = cand[0];
        for (int sI = 1; sI < KREP; sI++) {
            int best = 0;
            float bm = NINF;
            for (int c = 0; c < CC; c++)
                if (mind[c] > bm) { bm = mind[c]; best = c; }
            sel[sI] = cand[best];
            float cb = candf[best];
            for (int c = 0; c < CC; c++) mind[c] = fminf(mind[c], fabsf(candf[c] - cb));
            mind[best] = NINF;
        }
        for (int sI = 0; sI < KREP; sI++) {
            sels[sI] = sel[sI];
            o_idx[b * KREP + sI] = (float)sel[sI];
        }
    }
    __syncthreads();

    for (int kk = 0; kk < KREP; kk++) {
        int t = sels[kk];
        const float* src = vf + ((size_t)b * TT + t) * DV;
        float* dst = g_rep + (b * KREP + kk) * DV;
        if (tid < DV) dst[tid] = src[tid];
    }
}

// ================= kernel 4: post (QKV -> attn -> mean+oproj), persistent =================
// Register-blocked GEMM: 16 warps = 4 output-quads x 4 row-chunks.
// Warp owns 4 outputs x 12 rows (acc[4][12]); per kc reads 12 x-vec + 4 w-vec from smem.
__device__ void gemm_phase(const float* __restrict__ x, const float* __restrict__ w,
                           const float* __restrict__ bias, float* __restrict__ out,
                           int ostride, int ngroups, float4* xs, float4* ws) {
    int tid = threadIdx.x, lane = tid & 31, wid = tid >> 5;
    int quad = wid >> 2, chunk = wid & 3;
    for (int grp = blockIdx.x; grp < ngroups; grp += NBLK) {
        int obase = grp * 16;
        float acc[4][12];
#pragma unroll
        for (int j = 0; j < 4; j++)
#pragma unroll
            for (int r = 0; r < 12; r++) acc[j][r] = 0.f;

        for (int kc = 0; kc < 8; kc++) {
            __syncthreads();
#pragma unroll
            for (int t = 0; t < 3; t++) {
                int i = tid + t * 512;
                xs[i] = ((const float4*)(x + (size_t)(i >> 5) * DV + kc * 128))[i & 31];
            }
            ws[tid] = ((const float4*)(w + (size_t)(obase + (tid >> 5)) * DV + kc * 128))[tid & 31];
            __syncthreads();
            float4 wv0 = ws[(quad * 4 + 0) * 32 + lane];
            float4 wv1 = ws[(quad * 4 + 1) * 32 + lane];
            float4 wv2 = ws[(quad * 4 + 2) * 32 + lane];
            float4 wv3 = ws[(quad * 4 + 3) * 32 + lane];
#pragma unroll
            for (int r = 0; r < 12; r++) {
                float4 xv = xs[(chunk * 12 + r) * 32 + lane];
                acc[0][r] += wv0.x * xv.x + wv0.y * xv.y + wv0.z * xv.z + wv0.w * xv.w;
                acc[1][r] += wv1.x * xv.x + wv1.y * xv.y + wv1.z * xv.z + wv1.w * xv.w;
                acc[2][r] += wv2.x * xv.x + wv2.y * xv.y + wv2.z * xv.z + wv2.w * xv.w;
                acc[3][r] += wv3.x * xv.x + wv3.y * xv.y + wv3.z * xv.z + wv3.w * xv.w;
            }
        }
        float bs0 = bias[obase + quad * 4 + 0];
        float bs1 = bias[obase + quad * 4 + 1];
        float bs2 = bias[obase + quad * 4 + 2];
        float bs3 = bias[obase + quad * 4 + 3];
#pragma unroll
        for (int r = 0; r < 12; r++) {
            float s0 = warp_sum(acc[0][r]);
            float s1 = warp_sum(acc[1][r]);
            float s2 = warp_sum(acc[2][r]);
            float s3 = warp_sum(acc[3][r]);
            if (lane == r) {
                int row = chunk * 12 + r;
                float* dst = out + (size_t)row * ostride + obase + quad * 4;
                dst[0] = s0 + bs0;
                dst[1] = s1 + bs1;
                dst[2] = s2 + bs2;
                dst[3] = s3 + bs3;
            }
        }
    }
}

__global__ __launch_bounds__(512, 1) void k_post(
    const float* __restrict__ in_w,  const float* __restrict__ in_b,
    const float* __restrict__ out_w, const float* __restrict__ out_b,
    float* __restrict__ o_ref, float* __restrict__ o_attn) {

    __shared__ __align__(16) float4 xs[48 * 32];  // 24KB (also hosts attn tiles)
    __shared__ __align__(16) float4 ws[16 * 32];  // 8KB weight tile
    int tid = threadIdx.x, lane = tid & 31, wid = tid >> 5, blk = blockIdx.x;

    // ---- P0: QKV GEMM (192 groups of 16 outputs) ----
    gemm_phase(g_rep, in_w, in_b, g_qkv, 3 * DV, 192, xs, ws);
    gbar();

    // ---- P1: attention per (b,h) (blocks 0..63) ----
    if (blk < BB * NH) {
        int b = blk >> 3, h = blk & 7;
        float* qs = (float*)xs;
        float* ks = qs + KREP * HD;
        float* vs = ks + KREP * HD;
        for (int i = tid; i < KREP * HD; i += 512) {
            int row = i >> 7, d = i & 127;
            const float* base = g_qkv + (b * KREP + row) * 3 * DV + h * HD + d;
            qs[i] = base[0];
            ks[i] = base[DV];
            vs[i] = base[2 * DV];
        }
        __syncthreads();
        if (wid < KREP) {
            int i = wid;
            float sc[KREP];
            const float scale = 0.08838834764831845f;  // 1/sqrt(128)
            for (int j = 0; j < KREP; j++) {
                float acc = 0.f;
#pragma unroll
                for (int m = 0; m < 4; m++)
                    acc += qs[i * HD + lane + 32 * m] * ks[j * HD + lane + 32 * m];
                acc = warp_sum(acc);
                sc[j] = acc * scale;
            }
            float mx = sc[0];
            for (int j = 1; j < KREP; j++) mx = fmaxf(mx, sc[j]);
            float den = 0.f;
            for (int j = 0; j < KREP; j++) { sc[j] = expf(sc[j] - mx); den += sc[j]; }
            float rden = 1.f / den;
            for (int j = 0; j < KREP; j++) sc[j] *= rden;
            if (lane < KREP)
                g_attnw[((b * NH + h) * KREP + i) * KREP + lane] = sc[lane];
            for (int d = lane; d < HD; d += 32) {
                float o = 0.f;
                for (int j = 0; j < KREP; j++) o += sc[j] * vs[j * HD + d];
                g_ao[(b * KREP + i) * DV + h * HD + d] = o;
            }
        }
    }
    gbar();

    // ---- P2: attn-weight head-mean (blocks 0..7) + output projection (64 groups) ----
    if (blk < BB && tid < KREP * KREP) {
        int b = blk;
        float s = 0.f;
        for (int h = 0; h < NH; h++) s += g_attnw[(b * NH + h) * KREP * KREP + tid];
        o_attn[b * KREP * KREP + tid] = s * (1.f / (float)NH);
    }
    gemm_phase(g_ao, out_w, out_b, o_ref, DV, 64, xs, ws);
}

// ---------------- launcher ----------------
extern "C" void kernel_launch(void* const* d_in, const int* in_sizes, int n_in,
                              void* d_out, int out_size) {
    const float* vf    = (const float*)d_in[0];
    const float* qe    = (const float*)d_in[1];
    const float* mu_w1 = (const float*)d_in[2];
    const float* mu_b1 = (const float*)d_in[3];
    const float* mu_g  = (const float*)d_in[4];
    const float* mu_bt = (const float*)d_in[5];
    const float* mu_w2 = (const float*)d_in[6];
    const float* mu_b2 = (const float*)d_in[7];
    const float* sg_w1 = (const float*)d_in[8];
    const float* sg_b1 = (const float*)d_in[9];
    const float* sg_g  = (const float*)d_in[10];
    const float* sg_bt = (const float*)d_in[11];
    const float* sg_w2 = (const float*)d_in[12];
    const float* sg_b2 = (const float*)d_in[13];
    const float* in_w  = (const float*)d_in[14];
    const float* in_b  = (const float*)d_in[15];
    const float* out_w = (const float*)d_in[16];
    const float* out_b = (const float*)d_in[17];

    float* out = (float*)d_out;
    float* o_ref  = out;           // [8,6,1024]  49152
    float* o_idx  = out + 49152;   // [8,6]       48
    float* o_dist = out + 49200;   // [8,8192]    65536
    float* o_mu   = out + 114736;  // [8,1024]    8192
    float* o_sg   = out + 122928;  // [8,1024]    8192
    float* o_attn = out + 131120;  // [8,6,6]     288

    k_mlp<<<NBLK, 512>>>(qe, mu_w1, mu_b1, mu_g, mu_bt, mu_w2, mu_b2,
                         sg_w1, sg_b1, sg_g, sg_bt, sg_w2, sg_b2, o_mu, o_sg);
    k_dist<<<dim3(TT / 32, BB), 512>>>(vf, o_dist);
    k_select<<<BB, 1024>>>(o_dist, vf, o_idx);
    k_post<<<NBLK, 512>>>(in_w, in_b, out_w, out_b, o_ref, o_attn);
}

// round 10
// speedup vs baseline: 1.3510x; 1.0519x over previous
#include <cuda_runtime.h>
#include <math.h>

#define BB 8
#define TT 8192
#define DV 1024
#define DQ 768
#define KREP 6
#define NH 8
#define HD 128
#define CC 18
#define NB 2048
#define NBLK 128

// ---------------- scratch (no allocations allowed) ----------------
__device__ __align__(16) float g_pre[2 * BB * DV];
__device__ __align__(16) float g_h[2 * BB * DV];
__device__ __align__(16) float g_mu[BB * DV];
__device__ __align__(16) float g_isg[BB * DV];
__device__ __align__(16) float g_rep[BB * KREP * DV];
__device__ __align__(16) float g_qkv[BB * KREP * 3 * DV];
__device__ __align__(16) float g_ao[BB * KREP * DV];
__device__ float g_attnw[BB * NH * KREP * KREP];
__device__ unsigned g_cnt = 0, g_gen = 0;

__device__ __forceinline__ float warp_sum(float v) {
#pragma unroll
    for (int o = 16; o; o >>= 1) v += __shfl_xor_sync(0xffffffffu, v, o);
    return v;
}

// software grid barrier: NBLK blocks, all co-resident (1 block/SM)
__device__ __forceinline__ void gbar() {
    __syncthreads();
    if (threadIdx.x == 0) {
        volatile unsigned* vgen = &g_gen;
        unsigned gen = *vgen;
        __threadfence();
        unsigned t = atomicAdd(&g_cnt, 1u);
        if (t == NBLK - 1) {
            atomicExch(&g_cnt, 0u);
            __threadfence();
            atomicAdd(&g_gen, 1u);
        } else {
            while (*vgen == gen) { }
            __threadfence();
        }
    }
    __syncthreads();
}

// ================= kernel 1: MLP (lin1 -> LN -> lin2), persistent =================
__global__ __launch_bounds__(512, 1) void k_mlp(
    const float* __restrict__ qe,
    const float* __restrict__ mu_w1, const float* __restrict__ mu_b1,
    const float* __restrict__ mu_g,  const float* __restrict__ mu_bt,
    const float* __restrict__ mu_w2, const float* __restrict__ mu_b2,
    const float* __restrict__ sg_w1, const float* __restrict__ sg_b1,
    const float* __restrict__ sg_g,  const float* __restrict__ sg_bt,
    const float* __restrict__ sg_w2, const float* __restrict__ sg_b2,
    float* __restrict__ o_mu, float* __restrict__ o_sg) {

    __shared__ float red[16];
    __shared__ float sh_mean, sh_rstd;
    int tid = threadIdx.x, lane = tid & 31, wid = tid >> 5, blk = blockIdx.x;

    // ---- P0: Linear(768->1024) both branches: 16384 dots, 8/warp ----
    {
        int gw = blk * 16 + wid;  // 0..2047
#pragma unroll
        for (int d = 0; d < 8; d++) {
            int idx = gw * 8 + d;
            int br = idx >> 13;
            int rem = idx & 8191;
            int b = rem >> 10, o = rem & 1023;
            const float* w1 = br ? sg_w1 : mu_w1;
            const float* b1 = br ? sg_b1 : mu_b1;
            const float* x = qe + b * DQ;
            const float* wr = w1 + o * DQ;
            float acc = 0.f;
#pragma unroll
            for (int i = lane; i < DQ; i += 32) acc += wr[i] * x[i];
            acc = warp_sum(acc);
            if (lane == 0) g_pre[(br * BB + b) * DV + o] = acc + b1[o];
        }
    }
    gbar();

    // ---- P1: LayerNorm + ReLU (blocks 0..15, one per (b,br)) ----
    if (blk < 16) {
        int b = blk >> 1, br = blk & 1;
        const float* src = g_pre + (br * BB + b) * DV;
        float v0 = src[tid], v1 = src[tid + 512];
        float s = warp_sum(v0 + v1);
        if (lane == 0) red[wid] = s;
        __syncthreads();
        if (tid == 0) {
            float m = 0.f;
            for (int i = 0; i < 16; i++) m += red[i];
            sh_mean = m / (float)DV;
        }
        __syncthreads();
        float m = sh_mean;
        float d0 = v0 - m, d1 = v1 - m;
        float vv = warp_sum(d0 * d0 + d1 * d1);
        if (lane == 0) red[wid] = vv;
        __syncthreads();
        if (tid == 0) {
            float q = 0.f;
            for (int i = 0; i < 16; i++) q += red[i];
            sh_rstd = rsqrtf(q / (float)DV + 1e-5f);
        }
        __syncthreads();
        float rstd = sh_rstd;
        const float* g  = br ? sg_g  : mu_g;
        const float* bt = br ? sg_bt : mu_bt;
        float* dst = g_h + (br * BB + b) * DV;
        dst[tid]       = fmaxf(d0 * rstd * g[tid]       + bt[tid], 0.f);
        dst[tid + 512] = fmaxf(d1 * rstd * g[tid + 512] + bt[tid + 512], 0.f);
    }
    gbar();

    // ---- P2: Linear(1024->1024) + mu/softplus epilogue ----
    {
        int gw = blk * 16 + wid;
#pragma unroll
        for (int d = 0; d < 8; d++) {
            int idx = gw * 8 + d;
            int br = idx >> 13;
            int rem = idx & 8191;
            int b = rem >> 10, o = rem & 1023;
            const float* w2 = br ? sg_w2 : mu_w2;
            const float* b2 = br ? sg_b2 : mu_b2;
            const float* x = g_h + (br * BB + b) * DV;
            const float* wr = w2 + o * DV;
            float acc = 0.f;
#pragma unroll
            for (int i = lane; i < DV; i += 32) acc += wr[i] * x[i];
            acc = warp_sum(acc);
            if (lane == 0) {
                float val = acc + b2[o];
                if (br == 0) {
                    g_mu[b * DV + o] = val;
                    o_mu[b * DV + o] = val;
                } else {
                    float sp = fmaxf(val, 0.f) + log1pf(expf(-fabsf(val)));
                    float sg = sp + 1e-6f;
                    o_sg[b * DV + o] = sg;
                    g_isg[b * DV + o] = 1.f / sg;
                }
            }
        }
    }
}

// ================= kernel 2: Mahalanobis distance (wide grid, proven) =================
__global__ void k_dist(const float* __restrict__ vf, float* __restrict__ o_dist) {
    __shared__ float4 mus[DV / 4];
    __shared__ float4 iss[DV / 4];
    int b = blockIdx.y;
    int tid = threadIdx.x, lane = tid & 31, wid = tid >> 5;
    if (tid < 256) mus[tid] = ((const float4*)(g_mu + b * DV))[tid];
    else           iss[tid - 256] = ((const float4*)(g_isg + b * DV))[tid - 256];
    __syncthreads();

    int t0 = (blockIdx.x * 16 + wid) * 2;
    const float4* v0 = (const float4*)(vf + ((size_t)b * TT + t0) * DV);
    const float4* v1 = v0 + DV / 4;
    float a0 = 0.f, a1 = 0.f;
#pragma unroll
    for (int it = 0; it < 8; it++) {
        int i = lane + it * 32;
        float4 x0 = v0[i], x1 = v1[i], mm = mus[i], ss = iss[i];
        float d;
        d = x0.x - mm.x; a0 += d * d * ss.x;
        d = x0.y - mm.y; a0 += d * d * ss.y;
        d = x0.z - mm.z; a0 += d * d * ss.z;
        d = x0.w - mm.w; a0 += d * d * ss.w;
        d = x1.x - mm.x; a1 += d * d * ss.x;
        d = x1.y - mm.y; a1 += d * d * ss.y;
        d = x1.z - mm.z; a1 += d * d * ss.z;
        d = x1.w - mm.w; a1 += d * d * ss.w;
    }
    a0 = warp_sum(a0);
    a1 = warp_sum(a1);
    if (lane == 0) {
        o_dist[b * TT + t0]     = a0;
        o_dist[b * TT + t0 + 1] = a1;
    }
}

// ================= kernel 3: select (proven, 8 x 1024) =================
__device__ void radix_pass_s(const unsigned* __restrict__ keys,
                             int shift, int bits, bool first,
                             unsigned* hist, unsigned* wsum, unsigned* wpfx,
                             unsigned* sh_prefix, int* sh_k) {
    int tid = threadIdx.x, lane = tid & 31, wid = tid >> 5;
    hist[tid] = 0u;
    hist[tid + 1024] = 0u;
    __syncthreads();
    unsigned pfx = *sh_prefix;
    unsigned mask = (1u << bits) - 1u;
#pragma unroll
    for (int r = 0; r < 8; r++) {
        unsigned key = keys[tid + r * 1024];
        bool ok = first || ((key >> (shift + bits)) == pfx);
        if (ok) atomicAdd(&hist[(key >> shift) & mask], 1u);
    }
    __syncthreads();
    unsigned s0 = hist[tid * 2], s1 = hist[tid * 2 + 1];
    unsigned s = s0 + s1;
    unsigned inc = s;
#pragma unroll
    for (int o = 1; o < 32; o <<= 1) {
        unsigned n = __shfl_up_sync(0xffffffffu, inc, o);
        if (lane >= o) inc += n;
    }
    if (lane == 31) wsum[wid] = inc;
    __syncthreads();
    if (wid == 0) {
        unsigned v = wsum[lane];
        unsigned iw = v;
#pragma unroll
        for (int o = 1; o < 32; o <<= 1) {
            unsigned n = __shfl_up_sync(0xffffffffu, iw, o);
            if (lane >= o) iw += n;
        }
        wpfx[lane] = iw - v;
    }
    __syncthreads();
    unsigned base = wpfx[wid] + (inc - s);
    unsigned k = (unsigned)*sh_k;
    if (k >= base && k < base + s) {
        int bin = tid * 2;
        unsigned off = base;
        if (k >= off + s0) { off += s0; bin++; }
        *sh_prefix = (pfx << bits) | (unsigned)bin;
        *sh_k = (int)(k - off);
    }
    __syncthreads();
}

__global__ void k_select(const float* __restrict__ dist, const float* __restrict__ vf,
                         float* __restrict__ o_idx) {
    __shared__ unsigned keys[TT];
    __shared__ unsigned hist[NB];
    __shared__ unsigned wsum[32], wpfx[32];
    __shared__ unsigned sh_prefix;
    __shared__ int sh_k;
    __shared__ unsigned long long lessK[CC];
    __shared__ int eqIdx[64];
    __shared__ int sh_nless, sh_neq;
    __shared__ int sels[KREP];

    int b = blockIdx.x;
    int tid = threadIdx.x;
    const float* drow = dist + b * TT;

#pragma unroll
    for (int r = 0; r < 8; r++)
        keys[tid + r * 1024] = __float_as_uint(drow[tid + r * 1024]);
    if (tid == 0) { sh_prefix = 0u; sh_k = (TT - 1) / 2; }
    __syncthreads();

    radix_pass_s(keys, 21, 11, true,  hist, wsum, wpfx, &sh_prefix, &sh_k);
    radix_pass_s(keys, 10, 11, false, hist, wsum, wpfx, &sh_prefix, &sh_k);
    radix_pass_s(keys,  0, 10, false, hist, wsum, wpfx, &sh_prefix, &sh_k);
    float med = __uint_as_float(sh_prefix);
    __syncthreads();

#pragma unroll
    for (int r = 0; r < 8; r++) {
        int i = tid + r * 1024;
        keys[i] = __float_as_uint(fabsf(__uint_as_float(keys[i]) - med));
    }
    if (tid == 0) { sh_prefix = 0u; sh_k = CC - 1; sh_nless = 0; sh_neq = 0; }
    __syncthreads();

    radix_pass_s(keys, 21, 11, true,  hist, wsum, wpfx, &sh_prefix, &sh_k);
    radix_pass_s(keys, 10, 11, false, hist, wsum, wpfx, &sh_prefix, &sh_k);
    radix_pass_s(keys,  0, 10, false, hist, wsum, wpfx, &sh_prefix, &sh_k);
    unsigned vstar = sh_prefix;
    int n_eq_take = sh_k + 1;
    __syncthreads();

#pragma unroll
    for (int r = 0; r < 8; r++) {
        int i = tid + r * 1024;
        unsigned key = keys[i];
        if (key < vstar) {
            int p = atomicAdd(&sh_nless, 1);
            lessK[p] = ((unsigned long long)key << 13) | (unsigned)i;
        } else if (key == vstar) {
            int p = atomicAdd(&sh_neq, 1);
            if (p < 64) eqIdx[p] = i;
        }
    }
    __syncthreads();

    if (tid == 0) {
        int nless = sh_nless;
        int neq = sh_neq < 64 ? sh_neq : 64;
        for (int i = 1; i < nless; i++) {
            unsigned long long kv = lessK[i];
            int j = i - 1;
            while (j >= 0 && lessK[j] > kv) { lessK[j + 1] = lessK[j]; j--; }
            lessK[j + 1] = kv;
        }
        for (int i = 1; i < neq; i++) {
            int kv = eqIdx[i];
            int j = i - 1;
            while (j >= 0 && eqIdx[j] > kv) { eqIdx[j + 1] = eqIdx[j]; j--; }
            eqIdx[j + 1] = kv;
        }
        int cand[CC];
        for (int c = 0; c < nless; c++) cand[c] = (int)(lessK[c] & 0x1FFFull);
        for (int c = 0; c < n_eq_take && nless + c < CC; c++) cand[nless + c] = eqIdx[c];

        const float NINF = __int_as_float(0xff800000);
        float candf[CC], mind[CC];
        int sel[KREP];
        for (int c = 0; c < CC; c++) candf[c] = (float)cand[c];
        for (int c = 0; c < CC; c++) mind[c] = fabsf(candf[c] - candf[0]);
        mind[0] = NINF;
        sel[0] = cand[0];
        for (int sI = 1; sI < KREP; sI++) {
            int best = 0;
            float bm = NINF;
            for (int c = 0; c < CC; c++)
                if (mind[c] > bm) { bm = mind[c]; best = c; }
            sel[sI] = cand[best];
            float cb = candf[best];
            for (int c = 0; c < CC; c++) mind[c] = fminf(mind[c], fabsf(candf[c] - cb));
            mind[best] = NINF;
        }
        for (int sI = 0; sI < KREP; sI++) {
            sels[sI] = sel[sI];
            o_idx[b * KREP + sI] = (float)sel[sI];
        }
    }
    __syncthreads();

    for (int kk = 0; kk < KREP; kk++) {
        int t = sels[kk];
        const float* src = vf + ((size_t)b * TT + t) * DV;
        float* dst = g_rep + (b * KREP + kk) * DV;
        if (tid < DV) dst[tid] = src[tid];
    }
}

// ================= kernel 4: post (QKV -> attn -> mean+oproj), persistent 384thr =================
// Balanced 12-output groups, 12 warps = 3 output-quads x 4 row-chunks, acc[4][12].
// Register double-buffering: next kc tile LDG'd during current FMA.
__device__ void gemm_phase(const float* __restrict__ x, const float* __restrict__ w,
                           const float* __restrict__ bias, float* __restrict__ out,
                           int ostride, int nout, float4* xs, float4* ws) {
    int tid = threadIdx.x, lane = tid & 31, wid = tid >> 5;
    int oq = wid >> 2, chunk = wid & 3;
    int ngroups = (nout + 11) / 12;
    int worow = tid >> 5;   // ws row this thread loads (0..11)
    for (int grp = blockIdx.x; grp < ngroups; grp += NBLK) {
        int obase = grp * 12;
        bool wok = (obase + worow) < nout;
        const float4* wsrc = (const float4*)(w + (size_t)(wok ? obase + worow : 0) * DV);

        float acc[4][12];
#pragma unroll
        for (int j = 0; j < 4; j++)
#pragma unroll
            for (int r = 0; r < 12; r++) acc[j][r] = 0.f;

        // preload kc=0
        float4 px[4], pw;
#pragma unroll
        for (int j = 0; j < 4; j++) {
            int i = tid + j * 384;
            px[j] = ((const float4*)(x + (size_t)(i >> 5) * DV))[i & 31];
        }
        pw = wok ? wsrc[lane] : make_float4(0.f, 0.f, 0.f, 0.f);
        __syncthreads();   // prior consumers of xs/ws done
#pragma unroll
        for (int j = 0; j < 4; j++) xs[tid + j * 384] = px[j];
        ws[tid] = pw;
        __syncthreads();

        for (int kc = 0; kc < 8; kc++) {
            // prefetch next tile into registers (latency hidden by FMA below)
            if (kc < 7) {
#pragma unroll
                for (int j = 0; j < 4; j++) {
                    int i = tid + j * 384;
                    px[j] = ((const float4*)(x + (size_t)(i >> 5) * DV + (kc + 1) * 128))[i & 31];
                }
                pw = wok ? wsrc[(kc + 1) * 32 + lane] : make_float4(0.f, 0.f, 0.f, 0.f);
            }
            float4 wv0 = ws[(oq * 4 + 0) * 32 + lane];
            float4 wv1 = ws[(oq * 4 + 1) * 32 + lane];
            float4 wv2 = ws[(oq * 4 + 2) * 32 + lane];
            float4 wv3 = ws[(oq * 4 + 3) * 32 + lane];
#pragma unroll
            for (int r = 0; r < 12; r++) {
                float4 xv = xs[(chunk * 12 + r) * 32 + lane];
                acc[0][r] += wv0.x * xv.x + wv0.y * xv.y + wv0.z * xv.z + wv0.w * xv.w;
                acc[1][r] += wv1.x * xv.x + wv1.y * xv.y + wv1.z * xv.z + wv1.w * xv.w;
                acc[2][r] += wv2.x * xv.x + wv2.y * xv.y + wv2.z * xv.z + wv2.w * xv.w;
                acc[3][r] += wv3.x * xv.x + wv3.y * xv.y + wv3.z * xv.z + wv3.w * xv.w;
            }
            __syncthreads();
            if (kc < 7) {
#pragma unroll
                for (int j = 0; j < 4; j++) xs[tid + j * 384] = px[j];
                ws[tid] = pw;
                __syncthreads();
            }
        }

        float bs[4];
#pragma unroll
        for (int j = 0; j < 4; j++) {
            int o = obase + oq * 4 + j;
            bs[j] = (o < nout) ? bias[o] : 0.f;
        }
#pragma unroll
        for (int r = 0; r < 12; r++) {
            float s0 = warp_sum(acc[0][r]);
            float s1 = warp_sum(acc[1][r]);
            float s2 = warp_sum(acc[2][r]);
            float s3 = warp_sum(acc[3][r]);
            if (lane == r) {
                int row = chunk * 12 + r;
                int ob = obase + oq * 4;
                float* dst = out + (size_t)row * ostride + ob;
                if (ob + 0 < nout) dst[0] = s0 + bs[0];
                if (ob + 1 < nout) dst[1] = s1 + bs[1];
                if (ob + 2 < nout) dst[2] = s2 + bs[2];
                if (ob + 3 < nout) dst[3] = s3 + bs[3];
            }
        }
    }
}

__global__ __launch_bounds__(384, 1) void k_post(
    const float* __restrict__ in_w,  const float* __restrict__ in_b,
    const float* __restrict__ out_w, const float* __restrict__ out_b,
    float* __restrict__ o_ref, float* __restrict__ o_attn) {

    __shared__ __align__(16) float4 xs[48 * 32];  // 24KB (also hosts attn tiles)
    __shared__ __align__(16) float4 ws[12 * 32];  // 6KB weight tile
    int tid = threadIdx.x, lane = tid & 31, wid = tid >> 5, blk = blockIdx.x;

    // ---- P0: QKV GEMM (256 balanced groups of 12 outputs) ----
    gemm_phase(g_rep, in_w, in_b, g_qkv, 3 * DV, 3 * DV, xs, ws);
    gbar();

    // ---- P1: attention per (b,h) (blocks 0..63) ----
    if (blk < BB * NH) {
        int b = blk >> 3, h = blk & 7;
        float* qs = (float*)xs;
        float* ks = qs + KREP * HD;
        float* vs = ks + KREP * HD;
        for (int i = tid; i < KREP * HD; i += 384) {
            int row = i >> 7, d = i & 127;
            const float* base = g_qkv + (b * KREP + row) * 3 * DV + h * HD + d;
            qs[i] = base[0];
            ks[i] = base[DV];
            vs[i] = base[2 * DV];
        }
        __syncthreads();
        if (wid < KREP) {
            int i = wid;
            float sc[KREP];
            const float scale = 0.08838834764831845f;  // 1/sqrt(128)
            for (int j = 0; j < KREP; j++) {
                float acc = 0.f;
#pragma unroll
                for (int m = 0; m < 4; m++)
                    acc += qs[i * HD + lane + 32 * m] * ks[j * HD + lane + 32 * m];
                acc = warp_sum(acc);
                sc[j] = acc * scale;
            }
            float mx = sc[0];
            for (int j = 1; j < KREP; j++) mx = fmaxf(mx, sc[j]);
            float den = 0.f;
            for (int j = 0; j < KREP; j++) { sc[j] = expf(sc[j] - mx); den += sc[j]; }
            float rden = 1.f / den;
            for (int j = 0; j < KREP; j++) sc[j] *= rden;
            if (lane < KREP)
                g_attnw[((b * NH + h) * KREP + i) * KREP + lane] = sc[lane];
            for (int d = lane; d < HD; d += 32) {
                float o = 0.f;
                for (int j = 0; j < KREP; j++) o += sc[j] * vs[j * HD + d];
                g_ao[(b * KREP + i) * DV + h * HD + d] = o;
            }
        }
    }
    gbar();

    // ---- P2: attn-weight head-mean (blocks 0..7) + output projection ----
    if (blk < BB && tid < KREP * KREP) {
        int b = blk;
        float s = 0.f;
        for (int h = 0; h < NH; h++) s += g_attnw[(b * NH + h) * KREP * KREP + tid];
        o_attn[b * KREP * KREP + tid] = s * (1.f / (float)NH);
    }
    gemm_phase(g_ao, out_w, out_b, o_ref, DV, DV, xs, ws);
}

// ---------------- launcher ----------------
extern "C" void kernel_launch(void* const* d_in, const int* in_sizes, int n_in,
                              void* d_out, int out_size) {
    const float* vf    = (const float*)d_in[0];
    const float* qe    = (const float*)d_in[1];
    const float* mu_w1 = (const float*)d_in[2];
    const float* mu_b1 = (const float*)d_in[3];
    const float* mu_g  = (const float*)d_in[4];
    const float* mu_bt = (const float*)d_in[5];
    const float* mu_w2 = (const float*)d_in[6];
    const float* mu_b2 = (const float*)d_in[7];
    const float* sg_w1 = (const float*)d_in[8];
    const float* sg_b1 = (const float*)d_in[9];
    const float* sg_g  = (const float*)d_in[10];
    const float* sg_bt = (const float*)d_in[11];
    const float* sg_w2 = (const float*)d_in[12];
    const float* sg_b2 = (const float*)d_in[13];
    const float* in_w  = (const float*)d_in[14];
    const float* in_b  = (const float*)d_in[15];
    const float* out_w = (const float*)d_in[16];
    const float* out_b = (const float*)d_in[17];

    float* out = (float*)d_out;
    float* o_ref  = out;           // [8,6,1024]  49152
    float* o_idx  = out + 49152;   // [8,6]       48
    float* o_dist = out + 49200;   // [8,8192]    65536
    float* o_mu   = out + 114736;  // [8,1024]    8192
    float* o_sg   = out + 122928;  // [8,1024]    8192
    float* o_attn = out + 131120;  // [8,6,6]     288

    k_mlp<<<NBLK, 512>>>(qe, mu_w1, mu_b1, mu_g, mu_bt, mu_w2, mu_b2,
                         sg_w1, sg_b1, sg_g, sg_bt, sg_w2, sg_b2, o_mu, o_sg);
    k_dist<<<dim3(TT / 32, BB), 512>>>(vf, o_dist);
    k_select<<<BB, 1024>>>(o_dist, vf, o_idx);
    k_post<<<NBLK, 384>>>(in_w, in_b, out_w, out_b, o_ref, o_attn);
}